// round 8
// baseline (speedup 1.0000x reference)
#include <cuda_runtime.h>
#include <math_constants.h>

// ============================================================================
// Chamfer loss: ONE persistent kernel, exact uniform-grid NN, CSR layout.
// Grid = #SMs (co-resident), software grid barriers (hot spin), TPB=512.
// R8: G=256 (3.5x fewer candidates/query), 6-offset prefetch in fast path,
// position-based exact exit bound, generalized multi-elem P2 scan.
// Exactness: after scanning rows [cy-1,cy+1] x cols [cx-1,cx+1], any unscanned
// point is >= gb away where gb = per-axis min(cs+frac, 2cs-frac). Escape path
// (per 4-lane group): row-band scan, unscanned rows at |dy| have y-gap
// >= (dy-1)*cs; width W exact when (W*cs)^2 >= best, else widen & rescan.
// ============================================================================

#define G      256
#define NCELL  (G * G)
#define TC     (2 * NCELL)
#define TMAX   65536
#define TPB    512
#define NW     (TPB / 32)
#define MAXBLK 256
#define FULL   0xFFFFFFFFu

__device__ int          g_arr;
__device__ volatile int g_gen;
__device__ unsigned     g_blkbox[MAXBLK][4];
__device__ int          g_blksum[MAXBLK];
__device__ int          g_cnt[TC];
__device__ int          g_off[TC + 1];
__device__ int          g_cid[TMAX];
__device__ int          g_rank[TMAX];
__device__ float2       g_pts[TMAX];

static __device__ __forceinline__ unsigned f2ord(float f) {
    int b = __float_as_int(f);
    return (unsigned)b ^ (b < 0 ? 0xFFFFFFFFu : 0x80000000u);
}
static __device__ __forceinline__ float ord2f(unsigned u) {
    int b = (u & 0x80000000u) ? (int)(u ^ 0x80000000u) : (int)(~u);
    return __int_as_float(b);
}

static __device__ __forceinline__ void gridbar(int nblk) {
    __syncthreads();
    if (threadIdx.x == 0) {
        __threadfence();
        int g = g_gen;
        if (atomicAdd(&g_arr, 1) == nblk - 1) {
            g_arr = 0;
            __threadfence();
            g_gen = g + 1;
        } else {
            while (g_gen == g) { }
        }
    }
    __syncthreads();
}

// Block-wide exclusive scan; warp-uniform shfls, full masks.
static __device__ __forceinline__ int block_excl_scan(int v, int tid,
                                                      int* s_warp, int* total) {
    int lane = tid & 31, w = tid >> 5;
    int x = v;
#pragma unroll
    for (int o = 1; o < 32; o <<= 1) {
        int y = __shfl_up_sync(FULL, x, o);
        if (lane >= o) x += y;
    }
    if (lane == 31) s_warp[w] = x;
    __syncthreads();
    if (w == 0) {
        int y = (lane < NW) ? s_warp[lane] : 0;
#pragma unroll
        for (int o = 1; o < NW; o <<= 1) {
            int z = __shfl_up_sync(FULL, y, o);
            if (lane >= o) y += z;
        }
        if (lane < NW) s_warp[lane] = y;
    }
    __syncthreads();
    int base = w ? s_warp[w - 1] : 0;
    *total = s_warp[NW - 1];
    __syncthreads();
    return base + x - v;
}

static __device__ __forceinline__ int cell_of(float v, float o, float inv) {
    return min(G - 1, max(0, (int)((v - o) * inv)));
}

// ---------------------------------------------------------------------------
__global__ __launch_bounds__(TPB) void chamfer_fused(
    const float* __restrict__ A, int na,
    const float* __restrict__ B, int nb,
    float* __restrict__ out, int nblk)
{
    const int tid  = threadIdx.x;
    const int b    = blockIdx.x;
    const int gsz  = nblk * TPB;
    const int gtid = b * TPB + tid;
    const int total = na + nb;

    __shared__ int      s_warp[NW];
    __shared__ unsigned s_bb[4];
    __shared__ int      s_base;

    // ---------------- P0: zero counts, bbox partials, init out ----------------
    for (int i = gtid; i < TC; i += gsz) g_cnt[i] = 0;
    if (gtid == 0) { out[0] = 0.0f; g_off[TC] = total; }

    unsigned mnx = FULL, mny = FULL, mxx = 0u, mxy = 0u;
    for (int i = gtid; i < total; i += gsz) {
        const float2 p = (i < na) ? ((const float2*)A)[i]
                                  : ((const float2*)B)[i - na];
        unsigned ux = f2ord(p.x), uy = f2ord(p.y);
        mnx = min(mnx, ux); mny = min(mny, uy);
        mxx = max(mxx, ux); mxy = max(mxy, uy);
    }
#pragma unroll
    for (int o = 16; o > 0; o >>= 1) {
        mnx = min(mnx, __shfl_down_sync(FULL, mnx, o));
        mny = min(mny, __shfl_down_sync(FULL, mny, o));
        mxx = max(mxx, __shfl_down_sync(FULL, mxx, o));
        mxy = max(mxy, __shfl_down_sync(FULL, mxy, o));
    }
    {
        __shared__ unsigned sw[4][NW];
        int lane = tid & 31, w = tid >> 5;
        if (lane == 0) { sw[0][w] = mnx; sw[1][w] = mny; sw[2][w] = mxx; sw[3][w] = mxy; }
        __syncthreads();
        if (w == 0) {
            mnx = (lane < NW) ? sw[0][lane] : FULL;
            mny = (lane < NW) ? sw[1][lane] : FULL;
            mxx = (lane < NW) ? sw[2][lane] : 0u;
            mxy = (lane < NW) ? sw[3][lane] : 0u;
#pragma unroll
            for (int o = 16; o > 0; o >>= 1) {
                mnx = min(mnx, __shfl_down_sync(FULL, mnx, o));
                mny = min(mny, __shfl_down_sync(FULL, mny, o));
                mxx = max(mxx, __shfl_down_sync(FULL, mxx, o));
                mxy = max(mxy, __shfl_down_sync(FULL, mxy, o));
            }
            if (lane == 0) {
                g_blkbox[b][0] = mnx; g_blkbox[b][1] = mny;
                g_blkbox[b][2] = mxx; g_blkbox[b][3] = mxy;
            }
        }
    }
    gridbar(nblk);

    // ---------------- grid params ----------------
    if (tid < 32) {
        unsigned a0 = FULL, a1 = FULL, a2 = 0u, a3 = 0u;
        for (int k = tid; k < nblk; k += 32) {
            a0 = min(a0, g_blkbox[k][0]); a1 = min(a1, g_blkbox[k][1]);
            a2 = max(a2, g_blkbox[k][2]); a3 = max(a3, g_blkbox[k][3]);
        }
#pragma unroll
        for (int o = 16; o > 0; o >>= 1) {
            a0 = min(a0, __shfl_down_sync(FULL, a0, o));
            a1 = min(a1, __shfl_down_sync(FULL, a1, o));
            a2 = max(a2, __shfl_down_sync(FULL, a2, o));
            a3 = max(a3, __shfl_down_sync(FULL, a3, o));
        }
        if (tid == 0) { s_bb[0] = a0; s_bb[1] = a1; s_bb[2] = a2; s_bb[3] = a3; }
    }
    __syncthreads();
    const float x0 = ord2f(s_bb[0]);
    const float y0 = ord2f(s_bb[1]);
    const float L  = fmaxf(fmaxf(ord2f(s_bb[2]) - x0, ord2f(s_bb[3]) - y0), 1e-20f);
    const float cs = L / (float)G;
    const float inv = (float)G / L;

    // ---------------- P1: bin ----------------
    for (int i = gtid; i < total; i += gsz) {
        const float2 p = (i < na) ? ((const float2*)A)[i]
                                  : ((const float2*)B)[i - na];
        int s = (i < na) ? 0 : 1;
        int c = s * NCELL + cell_of(p.y, y0, inv) * G + cell_of(p.x, x0, inv);
        g_cid[i]  = c;
        g_rank[i] = atomicAdd(&g_cnt[c], 1);
    }
    gridbar(nblk);

    // ---------------- P2: per-block chunk scan (multi-elem per thread) -------
    const int cpb = (TC + nblk - 1) / nblk;      // 863 @ nblk=152
    const int per = (cpb + TPB - 1) / TPB;       // 2  @ nblk=152 (<=4 for >=64)
    const int cbeg = b * cpb;
    const int clim = min(cbeg + cpb, TC);
    const int tbeg = cbeg + tid * per;
    int loc[4];                                   // per <= 4 (nblk >= 64)
    int v = 0;
#pragma unroll
    for (int j = 0; j < 4; j++) {
        int idx = tbeg + j;
        loc[j] = (j < per && idx < clim) ? g_cnt[idx] : 0;
        v += loc[j];
    }
    int btot;
    int excl = block_excl_scan(v, tid, s_warp, &btot);
    if (tid == 0) g_blksum[b] = btot;
    gridbar(nblk);

    // ---------------- P3: block bases -> CSR offsets ----------------
    {
        int bv = (tid < nblk) ? g_blksum[tid] : 0;
        int t2;
        int e2 = block_excl_scan(bv, tid, s_warp, &t2);
        if (tid == b) s_base = e2;
        __syncthreads();
        int run = s_base + excl;
#pragma unroll
        for (int j = 0; j < 4; j++) {
            int idx = tbeg + j;
            if (j < per && idx < clim) { g_off[idx] = run; run += loc[j]; }
        }
    }
    gridbar(nblk);

    // ---------------- P4: scatter fill ----------------
    for (int i = gtid; i < total; i += gsz) {
        const float2 p = (i < na) ? ((const float2*)A)[i]
                                  : ((const float2*)B)[i - na];
        g_pts[g_off[g_cid[i]] + g_rank[i]] = p;
    }
    gridbar(nblk);

    // ---------------- P5: query (4 lanes/query) ----------------
    float acc = 0.0f;
    const int ntask = 4 * total;
    const unsigned gmask = 0xFu << ((tid & 31) & 28);
    const float INF = CUDART_INF_F;

    for (int task = gtid; task < ntask; task += gsz) {
        int q   = task >> 2;
        int sub = task & 3;
        float2 Q = g_pts[q];
        int cx = cell_of(Q.x, x0, inv);
        int cy = cell_of(Q.y, y0, inv);
        const int* __restrict__ off = g_off + ((q < na) ? NCELL : 0);

        float best = INF;

        // fast path: 3x3; all 6 row-offsets prefetched (independent loads)
        {
            int xlo = max(cx - 1, 0), xhi = min(cx + 1, G - 1);
            int sg[3], eg[3];
#pragma unroll
            for (int j = 0; j < 3; j++) {
                int yy = min(max(cy - 1 + j, 0), G - 1);  // dup rows at edges: min is idempotent
                sg[j] = off[yy * G + xlo];
                eg[j] = off[yy * G + xhi + 1];
            }
#pragma unroll
            for (int j = 0; j < 3; j++)
                for (int k = sg[j] + sub; k < eg[j]; k += 4) {
                    float2 p = g_pts[k];
                    float dx = Q.x - p.x, dy = Q.y - p.y;
                    best = fminf(best, fmaf(dx, dx, dy * dy));
                }
        }
        best = fminf(best, __shfl_xor_sync(gmask, best, 1));
        best = fminf(best, __shfl_xor_sync(gmask, best, 2));

        // exact exit bound from true position in cell (>= cs, avg ~1.25*cs)
        float fx = (Q.x - x0) - (float)cx * cs;
        float fy = (Q.y - y0) - (float)cy * cs;
        float gb = fminf(fminf(cs + fx, 2.0f * cs - fx),
                         fminf(cs + fy, 2.0f * cs - fy));
        gb = fmaxf(gb, 0.0f);

        // escape: row-band scan (group-uniform control flow)
        if (!(best <= gb * gb)) {
            int W = 12;
            for (;;) {
                if (best < INF) {
                    int Wn = (int)(sqrtf(best) * inv) + 2;
                    if (Wn > W) W = Wn;
                }
                if (W > G - 1) W = G - 1;
                int xlo = max(cx - W, 0), xhi = min(cx + W, G - 1);

                for (int dy = 0; dy < G; dy++) {
                    if (dy >= 1 && best < INF) {
                        float bb = (float)(dy - 1) * cs;
                        if (bb * bb >= best) break;
                    }
                    int yt = cy - dy, yb = cy + dy;
                    if (yt < 0 && yb > G - 1) break;
                    if (yt >= 0) {
                        int s0 = off[yt * G + xlo], e0 = off[yt * G + xhi + 1];
                        for (int k = s0 + sub; k < e0; k += 4) {
                            float2 p = g_pts[k];
                            float dx = Q.x - p.x, dyv = Q.y - p.y;
                            best = fminf(best, fmaf(dx, dx, dyv * dyv));
                        }
                    }
                    if (dy > 0 && yb <= G - 1) {
                        int s0 = off[yb * G + xlo], e0 = off[yb * G + xhi + 1];
                        for (int k = s0 + sub; k < e0; k += 4) {
                            float2 p = g_pts[k];
                            float dx = Q.x - p.x, dyv = Q.y - p.y;
                            best = fminf(best, fmaf(dx, dx, dyv * dyv));
                        }
                    }
                    best = fminf(best, __shfl_xor_sync(gmask, best, 1));
                    best = fminf(best, __shfl_xor_sync(gmask, best, 2));
                }

                bool fullwidth = (xlo == 0 && xhi == G - 1);
                if (best < INF) {
                    float wb = (float)W * cs;
                    if (wb * wb >= best || fullwidth) break;
                } else if (fullwidth) {
                    break;
                }
                W <<= 1;
            }
        }

        if (sub == 0) acc += sqrtf(best);
    }

    // Block sum -> one atomicAdd per block.
#pragma unroll
    for (int o = 16; o > 0; o >>= 1)
        acc += __shfl_down_sync(FULL, acc, o);
    {
        __shared__ float ws[NW];
        int lane = tid & 31, w = tid >> 5;
        if (lane == 0) ws[w] = acc;
        __syncthreads();
        if (w == 0) {
            acc = (lane < NW) ? ws[lane] : 0.0f;
#pragma unroll
            for (int o = 16; o > 0; o >>= 1)
                acc += __shfl_down_sync(FULL, acc, o);
            if (lane == 0) atomicAdd(out, acc);
        }
    }
}

// ---------------------------------------------------------------------------
extern "C" void kernel_launch(void* const* d_in, const int* in_sizes, int n_in,
                              void* d_out, int out_size) {
    const float* A = (const float*)d_in[0];
    const float* B = (const float*)d_in[1];
    int na = in_sizes[0] / 2;
    int nb = in_sizes[1] / 2;
    float* out = (float*)d_out;

    int sms = 0;
    if (cudaDeviceGetAttribute(&sms, cudaDevAttrMultiProcessorCount, 0) != cudaSuccess
        || sms <= 0) sms = 148;
    int nblk = sms;
    if (nblk > MAXBLK) nblk = MAXBLK;
    if (nblk < 64)     nblk = 64;      // keeps per <= 4 in the P2 scan

    chamfer_fused<<<nblk, TPB>>>(A, na, B, nb, out, nblk);
}

// round 9
// speedup vs baseline: 1.6786x; 1.6786x over previous
#include <cuda_runtime.h>
#include <math_constants.h>

// ============================================================================
// Chamfer loss: ONE persistent kernel, exact uniform-grid NN with CSR layout.
// Grid = #SMs (co-resident), software grid barriers (hot spin), TPB=512.
// Base = R6 (51.7us). R9 deltas (only): 6-offset prefetch in fast path;
// position-based exact exit bound gb = per-axis min(cs+frac, 2cs-frac).
// Exactness: after scanning the 3x3 block, any unscanned point is >= gb away.
// Escape (per 4-lane group): row-band scan; unscanned rows at |dy| have y-gap
// >= (dy-1)*cs; width W exact when (W*cs)^2 >= best, else widen & rescan.
// ============================================================================

#define G      128
#define NCELL  (G * G)
#define TC     (2 * NCELL)
#define TMAX   65536
#define TPB    512
#define NW     (TPB / 32)
#define MAXBLK 256
#define FULL   0xFFFFFFFFu

__device__ int          g_arr;
__device__ volatile int g_gen;
__device__ unsigned     g_blkbox[MAXBLK][4];
__device__ int          g_blksum[MAXBLK];
__device__ int          g_cnt[TC];
__device__ int          g_off[TC + 1];
__device__ int          g_cid[TMAX];
__device__ int          g_rank[TMAX];
__device__ float2       g_pts[TMAX];

static __device__ __forceinline__ unsigned f2ord(float f) {
    int b = __float_as_int(f);
    return (unsigned)b ^ (b < 0 ? 0xFFFFFFFFu : 0x80000000u);
}
static __device__ __forceinline__ float ord2f(unsigned u) {
    int b = (u & 0x80000000u) ? (int)(u ^ 0x80000000u) : (int)(~u);
    return __int_as_float(b);
}

static __device__ __forceinline__ void gridbar(int nblk) {
    __syncthreads();
    if (threadIdx.x == 0) {
        __threadfence();
        int g = g_gen;
        if (atomicAdd(&g_arr, 1) == nblk - 1) {
            g_arr = 0;
            __threadfence();
            g_gen = g + 1;
        } else {
            while (g_gen == g) { }
        }
    }
    __syncthreads();
}

// Block-wide exclusive scan; warp-uniform shfls, full masks.
static __device__ __forceinline__ int block_excl_scan(int v, int tid,
                                                      int* s_warp, int* total) {
    int lane = tid & 31, w = tid >> 5;
    int x = v;
#pragma unroll
    for (int o = 1; o < 32; o <<= 1) {
        int y = __shfl_up_sync(FULL, x, o);
        if (lane >= o) x += y;
    }
    if (lane == 31) s_warp[w] = x;
    __syncthreads();
    if (w == 0) {
        int y = (lane < NW) ? s_warp[lane] : 0;
#pragma unroll
        for (int o = 1; o < NW; o <<= 1) {
            int z = __shfl_up_sync(FULL, y, o);
            if (lane >= o) y += z;
        }
        if (lane < NW) s_warp[lane] = y;
    }
    __syncthreads();
    int base = w ? s_warp[w - 1] : 0;
    *total = s_warp[NW - 1];
    __syncthreads();
    return base + x - v;
}

static __device__ __forceinline__ int cell_of(float v, float o, float inv) {
    return min(G - 1, max(0, (int)((v - o) * inv)));
}

// ---------------------------------------------------------------------------
__global__ __launch_bounds__(TPB) void chamfer_fused(
    const float* __restrict__ A, int na,
    const float* __restrict__ B, int nb,
    float* __restrict__ out, int nblk)
{
    const int tid  = threadIdx.x;
    const int b    = blockIdx.x;
    const int gsz  = nblk * TPB;
    const int gtid = b * TPB + tid;
    const int total = na + nb;

    __shared__ int      s_warp[NW];
    __shared__ unsigned s_bb[4];
    __shared__ int      s_base;

    // ---------------- P0: zero counts, bbox partials, init out ----------------
    for (int i = gtid; i < TC; i += gsz) g_cnt[i] = 0;
    if (gtid == 0) { out[0] = 0.0f; g_off[TC] = total; }

    unsigned mnx = FULL, mny = FULL, mxx = 0u, mxy = 0u;
    for (int i = gtid; i < total; i += gsz) {
        const float2 p = (i < na) ? ((const float2*)A)[i]
                                  : ((const float2*)B)[i - na];
        unsigned ux = f2ord(p.x), uy = f2ord(p.y);
        mnx = min(mnx, ux); mny = min(mny, uy);
        mxx = max(mxx, ux); mxy = max(mxy, uy);
    }
#pragma unroll
    for (int o = 16; o > 0; o >>= 1) {
        mnx = min(mnx, __shfl_down_sync(FULL, mnx, o));
        mny = min(mny, __shfl_down_sync(FULL, mny, o));
        mxx = max(mxx, __shfl_down_sync(FULL, mxx, o));
        mxy = max(mxy, __shfl_down_sync(FULL, mxy, o));
    }
    {
        __shared__ unsigned sw[4][NW];
        int lane = tid & 31, w = tid >> 5;
        if (lane == 0) { sw[0][w] = mnx; sw[1][w] = mny; sw[2][w] = mxx; sw[3][w] = mxy; }
        __syncthreads();
        if (w == 0) {
            mnx = (lane < NW) ? sw[0][lane] : FULL;
            mny = (lane < NW) ? sw[1][lane] : FULL;
            mxx = (lane < NW) ? sw[2][lane] : 0u;
            mxy = (lane < NW) ? sw[3][lane] : 0u;
#pragma unroll
            for (int o = 16; o > 0; o >>= 1) {
                mnx = min(mnx, __shfl_down_sync(FULL, mnx, o));
                mny = min(mny, __shfl_down_sync(FULL, mny, o));
                mxx = max(mxx, __shfl_down_sync(FULL, mxx, o));
                mxy = max(mxy, __shfl_down_sync(FULL, mxy, o));
            }
            if (lane == 0) {
                g_blkbox[b][0] = mnx; g_blkbox[b][1] = mny;
                g_blkbox[b][2] = mxx; g_blkbox[b][3] = mxy;
            }
        }
    }
    gridbar(nblk);

    // ---------------- grid params ----------------
    if (tid < 32) {
        unsigned a0 = FULL, a1 = FULL, a2 = 0u, a3 = 0u;
        for (int k = tid; k < nblk; k += 32) {
            a0 = min(a0, g_blkbox[k][0]); a1 = min(a1, g_blkbox[k][1]);
            a2 = max(a2, g_blkbox[k][2]); a3 = max(a3, g_blkbox[k][3]);
        }
#pragma unroll
        for (int o = 16; o > 0; o >>= 1) {
            a0 = min(a0, __shfl_down_sync(FULL, a0, o));
            a1 = min(a1, __shfl_down_sync(FULL, a1, o));
            a2 = max(a2, __shfl_down_sync(FULL, a2, o));
            a3 = max(a3, __shfl_down_sync(FULL, a3, o));
        }
        if (tid == 0) { s_bb[0] = a0; s_bb[1] = a1; s_bb[2] = a2; s_bb[3] = a3; }
    }
    __syncthreads();
    const float x0 = ord2f(s_bb[0]);
    const float y0 = ord2f(s_bb[1]);
    const float L  = fmaxf(fmaxf(ord2f(s_bb[2]) - x0, ord2f(s_bb[3]) - y0), 1e-20f);
    const float cs = L / (float)G;
    const float inv = (float)G / L;

    // ---------------- P1: bin ----------------
    for (int i = gtid; i < total; i += gsz) {
        const float2 p = (i < na) ? ((const float2*)A)[i]
                                  : ((const float2*)B)[i - na];
        int s = (i < na) ? 0 : 1;
        int c = s * NCELL + cell_of(p.y, y0, inv) * G + cell_of(p.x, x0, inv);
        g_cid[i]  = c;
        g_rank[i] = atomicAdd(&g_cnt[c], 1);
    }
    gridbar(nblk);

    // ---------------- P2: per-block chunk scan ----------------
    const int cpb = (TC + nblk - 1) / nblk;   // 216 @ nblk=152, <= TPB
    const int idx = b * cpb + tid;
    int v = (tid < cpb && idx < TC) ? g_cnt[idx] : 0;
    int btot;
    int excl = block_excl_scan(v, tid, s_warp, &btot);
    if (tid == 0) g_blksum[b] = btot;
    gridbar(nblk);

    // ---------------- P3: block bases -> CSR offsets ----------------
    {
        int bv = (tid < nblk) ? g_blksum[tid] : 0;
        int t2;
        int e2 = block_excl_scan(bv, tid, s_warp, &t2);
        if (tid == b) s_base = e2;
        __syncthreads();
        if (tid < cpb && idx < TC) g_off[idx] = s_base + excl;
    }
    gridbar(nblk);

    // ---------------- P4: scatter fill ----------------
    for (int i = gtid; i < total; i += gsz) {
        const float2 p = (i < na) ? ((const float2*)A)[i]
                                  : ((const float2*)B)[i - na];
        g_pts[g_off[g_cid[i]] + g_rank[i]] = p;
    }
    gridbar(nblk);

    // ---------------- P5: query (4 lanes/query) ----------------
    float acc = 0.0f;
    const int ntask = 4 * total;
    const unsigned gmask = 0xFu << ((tid & 31) & 28);
    const float INF = CUDART_INF_F;

    for (int task = gtid; task < ntask; task += gsz) {
        int q   = task >> 2;
        int sub = task & 3;
        float2 Q = g_pts[q];
        int cx = cell_of(Q.x, x0, inv);
        int cy = cell_of(Q.y, y0, inv);
        const int* __restrict__ off = g_off + ((q < na) ? NCELL : 0);

        float best = INF;

        // fast path: 3x3; all 6 row-offsets prefetched (independent loads).
        // Edge rows clamp-duplicate (re-scan of same segment: harmless for min).
        {
            int xlo = max(cx - 1, 0), xhi = min(cx + 1, G - 1);
            int sg[3], eg[3];
#pragma unroll
            for (int j = 0; j < 3; j++) {
                int yy = min(max(cy - 1 + j, 0), G - 1);
                sg[j] = off[yy * G + xlo];
                eg[j] = off[yy * G + xhi + 1];
            }
#pragma unroll
            for (int j = 0; j < 3; j++)
                for (int k = sg[j] + sub; k < eg[j]; k += 4) {
                    float2 p = g_pts[k];
                    float dx = Q.x - p.x, dy = Q.y - p.y;
                    best = fminf(best, fmaf(dx, dx, dy * dy));
                }
        }
        best = fminf(best, __shfl_xor_sync(gmask, best, 1));
        best = fminf(best, __shfl_xor_sync(gmask, best, 2));

        // exact exit bound from true position in cell (cs..1.5cs, avg ~1.25cs)
        float fx = (Q.x - x0) - (float)cx * cs;
        float fy = (Q.y - y0) - (float)cy * cs;
        float gb = fminf(fminf(cs + fx, 2.0f * cs - fx),
                         fminf(cs + fy, 2.0f * cs - fy));
        gb = fmaxf(gb, 0.0f);

        // escape: row-band scan (group-uniform control flow)
        if (!(best <= gb * gb)) {
            int W = 12;
            for (;;) {
                if (best < INF) {
                    int Wn = (int)(sqrtf(best) * inv) + 2;
                    if (Wn > W) W = Wn;
                }
                if (W > G - 1) W = G - 1;
                int xlo = max(cx - W, 0), xhi = min(cx + W, G - 1);

                for (int dy = 0; dy < G; dy++) {
                    if (dy >= 1 && best < INF) {
                        float bb = (float)(dy - 1) * cs;
                        if (bb * bb >= best) break;
                    }
                    int yt = cy - dy, yb = cy + dy;
                    if (yt < 0 && yb > G - 1) break;
                    if (yt >= 0) {
                        int s0 = off[yt * G + xlo], e0 = off[yt * G + xhi + 1];
                        for (int k = s0 + sub; k < e0; k += 4) {
                            float2 p = g_pts[k];
                            float dx = Q.x - p.x, dyv = Q.y - p.y;
                            best = fminf(best, fmaf(dx, dx, dyv * dyv));
                        }
                    }
                    if (dy > 0 && yb <= G - 1) {
                        int s0 = off[yb * G + xlo], e0 = off[yb * G + xhi + 1];
                        for (int k = s0 + sub; k < e0; k += 4) {
                            float2 p = g_pts[k];
                            float dx = Q.x - p.x, dyv = Q.y - p.y;
                            best = fminf(best, fmaf(dx, dx, dyv * dyv));
                        }
                    }
                    best = fminf(best, __shfl_xor_sync(gmask, best, 1));
                    best = fminf(best, __shfl_xor_sync(gmask, best, 2));
                }

                bool fullwidth = (xlo == 0 && xhi == G - 1);
                if (best < INF) {
                    float wb = (float)W * cs;
                    if (wb * wb >= best || fullwidth) break;
                } else if (fullwidth) {
                    break;
                }
                W <<= 1;
            }
        }

        if (sub == 0) acc += sqrtf(best);
    }

    // Block sum -> one atomicAdd per block.
#pragma unroll
    for (int o = 16; o > 0; o >>= 1)
        acc += __shfl_down_sync(FULL, acc, o);
    {
        __shared__ float ws[NW];
        int lane = tid & 31, w = tid >> 5;
        if (lane == 0) ws[w] = acc;
        __syncthreads();
        if (w == 0) {
            acc = (lane < NW) ? ws[lane] : 0.0f;
#pragma unroll
            for (int o = 16; o > 0; o >>= 1)
                acc += __shfl_down_sync(FULL, acc, o);
            if (lane == 0) atomicAdd(out, acc);
        }
    }
}

// ---------------------------------------------------------------------------
extern "C" void kernel_launch(void* const* d_in, const int* in_sizes, int n_in,
                              void* d_out, int out_size) {
    const float* A = (const float*)d_in[0];
    const float* B = (const float*)d_in[1];
    int na = in_sizes[0] / 2;
    int nb = in_sizes[1] / 2;
    float* out = (float*)d_out;

    int sms = 0;
    if (cudaDeviceGetAttribute(&sms, cudaDevAttrMultiProcessorCount, 0) != cudaSuccess
        || sms <= 0) sms = 148;
    int nblk = sms;
    if (nblk > MAXBLK) nblk = MAXBLK;
    if (nblk < 64)     nblk = 64;      // keep cpb <= TPB for the chunk scan

    chamfer_fused<<<nblk, TPB>>>(A, na, B, nb, out, nblk);
}

// round 10
// speedup vs baseline: 2.0918x; 1.2461x over previous
#include <cuda_runtime.h>
#include <math_constants.h>

// ============================================================================
// Chamfer loss: ONE persistent kernel, exact uniform-grid NN with CSR layout.
// Grid = #SMs (co-resident), software grid barriers (hot spin), TPB=512.
// R10: fixed grid bounds (clamped indices stay EXACT: clamped/rounded points
// are always physically farther than their index implies, so pruning bounds
// remain conservative); self-cleaning counts (zeroed in P2 after read, so no
// init pass; __device__ globals are zero at module load); 4 barriers; dynamic
// warp-chunk task distribution in the query phase.
// Phases: P1 bin | P2 chunk scan (+self-zero) | P3 offsets | P4 fill | P5 query
// ============================================================================

#define G      128
#define NCELL  (G * G)
#define TC     (2 * NCELL)
#define TMAX   65536
#define TPB    512
#define NW     (TPB / 32)
#define MAXBLK 256
#define FULL   0xFFFFFFFFu

#define X0F  (-6.5f)
#define Y0F  (-6.5f)
#define CSF  (0.1015625f)              // 13/128, exact in binary
#define INVF (9.846153846153847f)      // 128/13

__device__ int          g_arr;
__device__ volatile int g_gen;
__device__ int          g_task;
__device__ int          g_blksum[MAXBLK];
__device__ int          g_cnt[TC];     // zero at load; self-cleaned each run
__device__ int          g_off[TC + 1];
__device__ int          g_cid[TMAX];
__device__ int          g_rank[TMAX];
__device__ float2       g_pts[TMAX];

static __device__ __forceinline__ void gridbar(int nblk) {
    __syncthreads();
    if (threadIdx.x == 0) {
        __threadfence();
        int g = g_gen;
        if (atomicAdd(&g_arr, 1) == nblk - 1) {
            g_arr = 0;
            __threadfence();
            g_gen = g + 1;
        } else {
            while (g_gen == g) { }
        }
    }
    __syncthreads();
}

// Block-wide exclusive scan; warp-uniform shfls, full masks.
static __device__ __forceinline__ int block_excl_scan(int v, int tid,
                                                      int* s_warp, int* total) {
    int lane = tid & 31, w = tid >> 5;
    int x = v;
#pragma unroll
    for (int o = 1; o < 32; o <<= 1) {
        int y = __shfl_up_sync(FULL, x, o);
        if (lane >= o) x += y;
    }
    if (lane == 31) s_warp[w] = x;
    __syncthreads();
    if (w == 0) {
        int y = (lane < NW) ? s_warp[lane] : 0;
#pragma unroll
        for (int o = 1; o < NW; o <<= 1) {
            int z = __shfl_up_sync(FULL, y, o);
            if (lane >= o) y += z;
        }
        if (lane < NW) s_warp[lane] = y;
    }
    __syncthreads();
    int base = w ? s_warp[w - 1] : 0;
    *total = s_warp[NW - 1];
    __syncthreads();
    return base + x - v;
}

static __device__ __forceinline__ int cell_clamp(float v, float o) {
    return min(G - 1, max(0, (int)((v - o) * INVF)));
}

// ---------------------------------------------------------------------------
__global__ __launch_bounds__(TPB) void chamfer_fused(
    const float* __restrict__ A, int na,
    const float* __restrict__ B, int nb,
    float* __restrict__ out, int nblk)
{
    const int tid  = threadIdx.x;
    const int b    = blockIdx.x;
    const int gsz  = nblk * TPB;
    const int gtid = b * TPB + tid;
    const int total = na + nb;

    __shared__ int s_warp[NW];
    __shared__ int s_base;

    // ---------------- P1: bin (g_cnt is zero from load / previous cleanup) ----
    if (gtid == 0) { out[0] = 0.0f; g_task = 0; g_off[TC] = total; }
    for (int i = gtid; i < total; i += gsz) {
        const float2 p = (i < na) ? ((const float2*)A)[i]
                                  : ((const float2*)B)[i - na];
        int s = (i < na) ? 0 : 1;
        int c = s * NCELL + cell_clamp(p.y, Y0F) * G + cell_clamp(p.x, X0F);
        g_cid[i]  = c;
        g_rank[i] = atomicAdd(&g_cnt[c], 1);
    }
    gridbar(nblk);

    // ---------------- P2: per-block chunk scan + self-zero ----------------
    const int cpb = (TC + nblk - 1) / nblk;   // 216 @ nblk=152, <= TPB
    const int idx = b * cpb + tid;
    const bool own = (tid < cpb && idx < TC);
    int v = own ? g_cnt[idx] : 0;
    if (own) g_cnt[idx] = 0;                  // clean for next launch
    int btot;
    int excl = block_excl_scan(v, tid, s_warp, &btot);
    if (tid == 0) g_blksum[b] = btot;
    gridbar(nblk);

    // ---------------- P3: block bases -> CSR offsets ----------------
    {
        int bv = (tid < nblk) ? g_blksum[tid] : 0;
        int t2;
        int e2 = block_excl_scan(bv, tid, s_warp, &t2);
        if (tid == b) s_base = e2;
        __syncthreads();
        if (own) g_off[idx] = s_base + excl;
    }
    gridbar(nblk);

    // ---------------- P4: scatter fill ----------------
    for (int i = gtid; i < total; i += gsz) {
        const float2 p = (i < na) ? ((const float2*)A)[i]
                                  : ((const float2*)B)[i - na];
        g_pts[g_off[g_cid[i]] + g_rank[i]] = p;
    }
    gridbar(nblk);

    // ---------------- P5: query (4 lanes/query; dynamic warp chunks) ---------
    float acc = 0.0f;
    const int ntask = 4 * total;              // multiple of 4
    const int lane  = tid & 31;
    const unsigned gmask = 0xFu << (lane & 28);
    const float INF = CUDART_INF_F;

    for (;;) {
        int chunk;
        if (lane == 0) chunk = atomicAdd(&g_task, 32);
        chunk = __shfl_sync(FULL, chunk, 0);
        if (chunk >= ntask) break;

        int task = chunk + lane;
        bool valid = task < ntask;
        if (!valid) task = ntask - 1;         // clamped lanes: complete group, discarded
        int q   = task >> 2;
        int sub = task & 3;
        float2 Q = g_pts[q];
        int cx = cell_clamp(Q.x, X0F);
        int cy = cell_clamp(Q.y, Y0F);
        const int* __restrict__ off = g_off + ((q < na) ? NCELL : 0);

        float best = INF;

        // fast path: 3x3; all 6 row-offsets prefetched (independent loads).
        {
            int xlo = max(cx - 1, 0), xhi = min(cx + 1, G - 1);
            int sg[3], eg[3];
#pragma unroll
            for (int j = 0; j < 3; j++) {
                int yy = min(max(cy - 1 + j, 0), G - 1);
                sg[j] = off[yy * G + xlo];
                eg[j] = off[yy * G + xhi + 1];
            }
#pragma unroll
            for (int j = 0; j < 3; j++)
                for (int k = sg[j] + sub; k < eg[j]; k += 4) {
                    float2 p = g_pts[k];
                    float dx = Q.x - p.x, dy = Q.y - p.y;
                    best = fminf(best, fmaf(dx, dx, dy * dy));
                }
        }
        best = fminf(best, __shfl_xor_sync(gmask, best, 1));
        best = fminf(best, __shfl_xor_sync(gmask, best, 2));

        // exact exit bound from true position in cell (conservative for any f)
        float fx = (Q.x - X0F) - (float)cx * CSF;
        float fy = (Q.y - Y0F) - (float)cy * CSF;
        float gb = fminf(fminf(CSF + fx, 2.0f * CSF - fx),
                         fminf(CSF + fy, 2.0f * CSF - fy));
        gb = fmaxf(gb, 0.0f);

        // escape: row-band scan (group-uniform control flow)
        if (!(best <= gb * gb)) {
            int W = 12;
            for (;;) {
                if (best < INF) {
                    int Wn = (int)(sqrtf(best) * INVF) + 2;
                    if (Wn > W) W = Wn;
                }
                if (W > G - 1) W = G - 1;
                int xlo = max(cx - W, 0), xhi = min(cx + W, G - 1);

                for (int dy = 0; dy < G; dy++) {
                    if (dy >= 1 && best < INF) {
                        float bb = (float)(dy - 1) * CSF;
                        if (bb * bb >= best) break;
                    }
                    int yt = cy - dy, yb = cy + dy;
                    if (yt < 0 && yb > G - 1) break;
                    if (yt >= 0) {
                        int s0 = off[yt * G + xlo], e0 = off[yt * G + xhi + 1];
                        for (int k = s0 + sub; k < e0; k += 4) {
                            float2 p = g_pts[k];
                            float dx = Q.x - p.x, dyv = Q.y - p.y;
                            best = fminf(best, fmaf(dx, dx, dyv * dyv));
                        }
                    }
                    if (dy > 0 && yb <= G - 1) {
                        int s0 = off[yb * G + xlo], e0 = off[yb * G + xhi + 1];
                        for (int k = s0 + sub; k < e0; k += 4) {
                            float2 p = g_pts[k];
                            float dx = Q.x - p.x, dyv = Q.y - p.y;
                            best = fminf(best, fmaf(dx, dx, dyv * dyv));
                        }
                    }
                    best = fminf(best, __shfl_xor_sync(gmask, best, 1));
                    best = fminf(best, __shfl_xor_sync(gmask, best, 2));
                }

                bool fullwidth = (xlo == 0 && xhi == G - 1);
                if (best < INF) {
                    float wb = (float)W * CSF;
                    if (wb * wb >= best || fullwidth) break;
                } else if (fullwidth) {
                    break;
                }
                W <<= 1;
            }
        }

        if (sub == 0 && valid) acc += sqrtf(best);
    }

    // Block sum -> one atomicAdd per block.
#pragma unroll
    for (int o = 16; o > 0; o >>= 1)
        acc += __shfl_down_sync(FULL, acc, o);
    {
        __shared__ float ws[NW];
        int w = tid >> 5;
        if (lane == 0) ws[w] = acc;
        __syncthreads();
        if (w == 0) {
            acc = (lane < NW) ? ws[lane] : 0.0f;
#pragma unroll
            for (int o = 16; o > 0; o >>= 1)
                acc += __shfl_down_sync(FULL, acc, o);
            if (lane == 0) atomicAdd(out, acc);
        }
    }
}

// ---------------------------------------------------------------------------
extern "C" void kernel_launch(void* const* d_in, const int* in_sizes, int n_in,
                              void* d_out, int out_size) {
    const float* A = (const float*)d_in[0];
    const float* B = (const float*)d_in[1];
    int na = in_sizes[0] / 2;
    int nb = in_sizes[1] / 2;
    float* out = (float*)d_out;

    int sms = 0;
    if (cudaDeviceGetAttribute(&sms, cudaDevAttrMultiProcessorCount, 0) != cudaSuccess
        || sms <= 0) sms = 148;
    int nblk = sms;
    if (nblk > MAXBLK) nblk = MAXBLK;
    if (nblk < 64)     nblk = 64;      // keep cpb <= TPB for the chunk scan

    chamfer_fused<<<nblk, TPB>>>(A, na, B, nb, out, nblk);
}